// round 14
// baseline (speedup 1.0000x reference)
#include <cuda_runtime.h>
#include <cuda_bf16.h>
#include <cstdint>

#define BB 128
#define SS 1024
#define EE 512
#define HH 512
#define GG 2048
#define BSH (128*1024*512)

// ---------------- device scratch ----------------
__device__ float    g_xg[(size_t)SS * BB * GG];     // 1 GiB Xg[t][b][g]
__device__ uint32_t g_esh[(size_t)BB * SS * 256];   // embed bf16x2 hi plane (128 MB)
__device__ uint32_t g_esl[(size_t)BB * SS * 256];   // embed lo plane
__device__ uint32_t g_wsh[2 * GG * 256];            // W_ih hi plane (4 MB)
__device__ uint32_t g_wsl[2 * GG * 256];
__device__ uint32_t g_hsh[2 * BB * 256];            // h hi plane, double buffered
__device__ uint32_t g_hsl[2 * BB * 256];
__device__ float    g_c[BB * HH];
__device__ float    g_biasc[2 * GG];
__device__ int      g_perm[SS * BB];
__device__ int      g_cnt0[SS];
__device__ int      g_flat[1025 * 128];
__device__ int      g_total0_pad;
__device__ unsigned g_count;
__device__ unsigned g_release;

// ---------------- helpers ----------------
__device__ __forceinline__ void split2(float x, float y, uint32_t& h, uint32_t& l) {
    unsigned short hx = __bfloat16_as_ushort(__float2bfloat16(x));
    unsigned short hy = __bfloat16_as_ushort(__float2bfloat16(y));
    float fx = __bfloat162float(__ushort_as_bfloat16(hx));
    float fy = __bfloat162float(__ushort_as_bfloat16(hy));
    unsigned short lx = __bfloat16_as_ushort(__float2bfloat16(x - fx));
    unsigned short ly = __bfloat16_as_ushort(__float2bfloat16(y - fy));
    h = ((uint32_t)hy << 16) | hx;
    l = ((uint32_t)ly << 16) | lx;
}

__device__ __forceinline__ void mma16(float* d, uint32_t a0, uint32_t a1, uint32_t a2,
                                      uint32_t a3, uint32_t b0, uint32_t b1) {
    asm volatile(
        "mma.sync.aligned.m16n8k16.row.col.f32.bf16.bf16.f32 "
        "{%0,%1,%2,%3},{%4,%5,%6,%7},{%8,%9},{%0,%1,%2,%3};\n"
        : "+f"(d[0]), "+f"(d[1]), "+f"(d[2]), "+f"(d[3])
        : "r"(a0), "r"(a1), "r"(a2), "r"(a3), "r"(b0), "r"(b1));
}

__device__ __forceinline__ void cpa16(uint32_t dst, const void* src, uint32_t nbytes) {
    asm volatile("cp.async.cg.shared.global [%0], [%1], 16, %2;\n"
                 :: "r"(dst), "l"(src), "r"(nbytes));
}
#define CP_COMMIT() asm volatile("cp.async.commit_group;\n")
#define CP_WAIT(n)  asm volatile("cp.async.wait_group %0;\n" :: "n"(n))

__device__ __forceinline__ float sigm(float x) {
    return __fdividef(1.f, 1.f + __expf(-x));
}
__device__ __forceinline__ float bf_lo(uint32_t u) {
    return __bfloat162float(__ushort_as_bfloat16((unsigned short)(u & 0xffffu)));
}
__device__ __forceinline__ float bf_hi(uint32_t u) {
    return __bfloat162float(__ushort_as_bfloat16((unsigned short)(u >> 16)));
}

// ---------------- k_init: pre-split operands + state init ----------------
// grid 2120 x 256
__global__ void k_init(const float* __restrict__ bih, const float* __restrict__ bhh,
                       const float* __restrict__ embed, const float* __restrict__ Wih) {
    int bx = blockIdx.x, tid = threadIdx.x;
    if (bx < 2048) {                       // embed: 33,554,432 float2
        int p0 = bx * 256 + tid;
        const float2* e2 = (const float2*)embed;
#pragma unroll 4
        for (int j = 0; j < 64; j++) {
            int p = p0 + j * 524288;
            float2 v = __ldg(e2 + p);
            uint32_t h, l; split2(v.x, v.y, h, l);
            g_esh[p] = h; g_esl[p] = l;
        }
    } else if (bx < 2112) {                // W_ih: 1,048,576 float2
        int p0 = (bx - 2048) * 256 + tid;
        const float2* w2 = (const float2*)Wih;
#pragma unroll 4
        for (int j = 0; j < 64; j++) {
            int p = p0 + j * 16384;
            float2 v = __ldg(w2 + p);
            uint32_t h, l; split2(v.x, v.y, h, l);
            g_wsh[p] = h; g_wsl[p] = l;
        }
    } else {                               // state init (8 blocks x 256 = 2048 thr)
        int i0 = (bx - 2112) * 256 + tid;
#pragma unroll
        for (int j = 0; j < 2; j++) { int i = i0 + j * 2048; g_biasc[i] = bih[i] + bhh[i]; }
#pragma unroll
        for (int j = 0; j < 32; j++) { int i = i0 + j * 2048; g_c[i] = 0.f; }
#pragma unroll
        for (int j = 0; j < 32; j++) { int i = i0 + j * 2048; g_hsh[i] = 0u; g_hsl[i] = 0u; }
        if (bx == 2112 && tid == 0) { g_count = 0u; g_release = 0u; }
    }
}

// ---------------- k_setup: perm + scan + flat fused (1 block x 1024) ----------------
__global__ void k_setup(const int* __restrict__ inp) {
    __shared__ int s[1024];
    int t = threadIdx.x;
    int i0 = 0, i1 = 128;
    for (int b = 0; b < 128; b++) {
        int v = inp[b * SS + t] & 1;
        if (!v) g_perm[t * 128 + i0++] = b;
        else    g_perm[t * 128 + --i1] = b;
    }
    g_cnt0[t] = i0;
    s[t] = i0;
    __syncthreads();
    for (int off = 1; off < 1024; off <<= 1) {
        int v = (t >= off) ? s[t - off] : 0;
        __syncthreads();
        s[t] += v;
        __syncthreads();
    }
    int tot0 = s[1023];
    int t0p = (tot0 + 127) & ~127;
    int base0 = s[t] - i0;
    int base1 = t0p + 128 * t - base0;
    for (int i = 0; i < i0; i++)
        g_flat[base0 + i] = (g_perm[t * 128 + i] << 10) | t;
    for (int i = i0; i < 128; i++)
        g_flat[base1 + (i - i0)] = (g_perm[t * 128 + i] << 10) | t;
    if (t == 0) g_total0_pad = t0p;
    int mid = t0p - tot0;
    if (t < mid) g_flat[tot0 + t] = -1;
    int fe = t0p + (SS * BB - tot0);
    int tail = 1025 * 128 - fe;
    if (t < tail) g_flat[fe + t] = -1;
}

// ---------------- phase 1: Xg = W_ih[cell] x + bias  (bf16x3, cp.async from planes) ----------------
// grid (32, 1025), 256 thr. Tile 128 tokens x 64 gate cols, K=512 in 16 stages of 32.
// u32: sAh 2*128*20=5120, sAl 5120, sBh 2*64*20=2560, sBl 2560, toks 128
#define SMEM1 ((5120 + 5120 + 2560 + 2560 + 128) * 4)

__global__ __launch_bounds__(256) void k_phase1() {
    extern __shared__ uint32_t smu[];
    uint32_t* sAh = smu;
    uint32_t* sAl = sAh + 5120;
    uint32_t* sBh = sAl + 5120;
    uint32_t* sBl = sBh + 2560;
    int*      toks = (int*)(sBl + 2560);

    const int tid = threadIdx.x, lane = tid & 31, warp = tid >> 5;
    const int wm = warp & 3, wn = warp >> 2;
    const int m0 = blockIdx.y * 128, n0 = blockIdx.x * 64;

    if (tid < 128) toks[tid] = g_flat[m0 + tid];
    __syncthreads();
    const int cell = (m0 >= g_total0_pad) ? 1 : 0;
    const float* biasb = g_biasc + cell * GG;

    // cp.async source setup: A rows ra0, ra1 (q-th 16B chunk); B row rb
    const int q = tid & 3;
    const int ra0 = tid >> 2, ra1 = 64 + ra0, rb = tid >> 2;
    const int tok0 = toks[ra0], tok1 = toks[ra1];
    const uint32_t szA0 = (tok0 >= 0) ? 16u : 0u;
    const uint32_t szA1 = (tok1 >= 0) ? 16u : 0u;
    const uint32_t* s0h = g_esh + (size_t)max(tok0, 0) * 256 + q * 4;
    const uint32_t* s0l = g_esl + (size_t)max(tok0, 0) * 256 + q * 4;
    const uint32_t* s1h = g_esh + (size_t)max(tok1, 0) * 256 + q * 4;
    const uint32_t* s1l = g_esl + (size_t)max(tok1, 0) * 256 + q * 4;
    const uint32_t* sbh = g_wsh + ((size_t)cell * GG + n0 + rb) * 256 + q * 4;
    const uint32_t* sbl = g_wsl + ((size_t)cell * GG + n0 + rb) * 256 + q * 4;

    const uint32_t aAh = (uint32_t)__cvta_generic_to_shared(sAh);
    const uint32_t aAl = (uint32_t)__cvta_generic_to_shared(sAl);
    const uint32_t aBh = (uint32_t)__cvta_generic_to_shared(sBh);
    const uint32_t aBl = (uint32_t)__cvta_generic_to_shared(sBl);
    const uint32_t dA0 = (ra0 * 20 + q * 4) * 4;
    const uint32_t dA1 = (ra1 * 20 + q * 4) * 4;
    const uint32_t dB  = (rb * 20 + q * 4) * 4;

    auto fill = [&](int s) {
        int buf = s & 1, ko = s * 16;
        uint32_t bo = buf * 2560 * 4, bo2 = buf * 1280 * 4;
        cpa16(aAh + bo + dA0, s0h + ko, szA0);
        cpa16(aAh + bo + dA1, s1h + ko, szA1);
        cpa16(aAl + bo + dA0, s0l + ko, szA0);
        cpa16(aAl + bo + dA1, s1l + ko, szA1);
        cpa16(aBh + bo2 + dB, sbh + ko, 16u);
        cpa16(aBl + bo2 + dB, sbl + ko, 16u);
        CP_COMMIT();
    };

    float d[2][4][4];
#pragma unroll
    for (int a = 0; a < 2; a++)
#pragma unroll
        for (int b = 0; b < 4; b++)
#pragma unroll
            for (int c = 0; c < 4; c++) d[a][b][c] = 0.f;

    const int cq = lane & 3, rq = lane >> 2;

    fill(0);
    for (int ks = 0; ks < 16; ks++) {
        if (ks < 15) { fill(ks + 1); CP_WAIT(1); }
        else         { CP_WAIT(0); }
        __syncthreads();
        const int buf = ks & 1;
        const uint32_t* Ah = sAh + buf * 2560;
        const uint32_t* Al = sAl + buf * 2560;
        const uint32_t* Bh = sBh + buf * 1280;
        const uint32_t* Bl = sBl + buf * 1280;
#pragma unroll
        for (int kc = 0; kc < 2; kc++) {
            int kb = kc * 8 + cq;
            uint32_t bh[4][2], bl[4][2];
#pragma unroll
            for (int nt = 0; nt < 4; nt++) {
                int n = wn * 32 + nt * 8 + rq;
                bh[nt][0] = Bh[n * 20 + kb]; bh[nt][1] = Bh[n * 20 + kb + 4];
                bl[nt][0] = Bl[n * 20 + kb]; bl[nt][1] = Bl[n * 20 + kb + 4];
            }
#pragma unroll
            for (int mt = 0; mt < 2; mt++) {
                int r = wm * 32 + mt * 16 + rq;
                uint32_t ah0 = Ah[r * 20 + kb],     ah1 = Ah[(r + 8) * 20 + kb];
                uint32_t ah2 = Ah[r * 20 + kb + 4], ah3 = Ah[(r + 8) * 20 + kb + 4];
                uint32_t al0 = Al[r * 20 + kb],     al1 = Al[(r + 8) * 20 + kb];
                uint32_t al2 = Al[r * 20 + kb + 4], al3 = Al[(r + 8) * 20 + kb + 4];
#pragma unroll
                for (int nt = 0; nt < 4; nt++) {
                    mma16(d[mt][nt], ah0, ah1, ah2, ah3, bh[nt][0], bh[nt][1]);
                    mma16(d[mt][nt], ah0, ah1, ah2, ah3, bl[nt][0], bl[nt][1]);
                    mma16(d[mt][nt], al0, al1, al2, al3, bh[nt][0], bh[nt][1]);
                }
            }
        }
        __syncthreads();
    }

#pragma unroll
    for (int mt = 0; mt < 2; mt++)
#pragma unroll
        for (int half = 0; half < 2; half++) {
            int r = wm * 32 + mt * 16 + rq + half * 8;
            int tok = toks[r];
            if (tok < 0) continue;
            int tt = tok & 1023, b = tok >> 10;
            size_t base = ((size_t)(tt * 128 + b)) * GG;
#pragma unroll
            for (int nt = 0; nt < 4; nt++) {
                int g0 = n0 + wn * 32 + nt * 8 + cq * 2;
                float2 v;
                v.x = d[mt][nt][half * 2 + 0] + biasb[g0];
                v.y = d[mt][nt][half * 2 + 1] + biasb[g0 + 1];
                *(float2*)(g_xg + base + g0) = v;
            }
        }
}

// ---------------- phase 2: persistent recurrence (cp.async staged, zero-cvt loop) ----------------
// 128 CTAs: cell = bx>>6, j0 = (bx&63)*8. N=32 cols ({i,f,g,o} x 8), K=512.
// smem: sW uint2 32x261 (66816 B) + sAh/sAl u32 2x128x20 each (40960 B) + perm (512 B)
#define SMEM2 (8352*8 + 2*5120*4 + 128*4)

__global__ __launch_bounds__(256, 1) void k_phase2(const float* __restrict__ Whh,
                                                   float* __restrict__ out) {
    extern __shared__ uint32_t smu[];
    uint2*    sW   = (uint2*)smu;            // 32 x 261
    uint32_t* sAh  = smu + 16704;            // 2 x 128 x 20
    uint32_t* sAl  = sAh + 5120;
    int*      permS = (int*)(sAl + 5120);

    const int tid = threadIdx.x, lane = tid & 31, w = tid >> 5;
    const int cq = lane & 3, rq = lane >> 2;
    const int cell = blockIdx.x >> 6;
    const int j0 = (blockIdx.x & 63) * 8;

    for (int idx = tid; idx < 32 * 256; idx += 256) {
        int n = idx >> 8, kp = idx & 255;
        int grow = ((n >> 3) << 9) + j0 + (n & 7);
        float2 v = *(const float2*)(Whh + ((size_t)cell * GG + grow) * HH + kp * 2);
        uint32_t h, l; split2(v.x, v.y, h, l);
        sW[n * 261 + kp] = make_uint2(h, l);
    }
    __syncthreads();

    const uint32_t aAh = (uint32_t)__cvta_generic_to_shared(sAh);
    const uint32_t aAl = (uint32_t)__cvta_generic_to_shared(sAl);
    const int q = tid & 3;
    const int r0 = tid >> 2, r1 = 64 + r0;
    const uint32_t dA0 = (r0 * 20 + q * 4) * 4;
    const uint32_t dA1 = (r1 * 20 + q * 4) * 4;

    for (int t = 0; t < SS; t++) {
        if (tid == 0) {
            unsigned r;
            do { asm volatile("ld.acquire.gpu.u32 %0, [%1];" : "=r"(r) : "l"(&g_release)); }
            while (r < (unsigned)t);
        }
        __syncthreads();

        int cnt0 = g_cnt0[t];
        int Mc = cell ? (128 - cnt0) : cnt0;
        int base = cell ? cnt0 : 0;
        if (tid < 128) permS[tid] = (tid < Mc) ? g_perm[t * 128 + base + tid] : 0;
        __syncthreads();

        const int Mpad = (Mc + 15) & ~15;
        const int rp = (t & 1) ^ 1;
        const bool act = (w * 16) < Mc;

        const uint32_t szA0 = (r0 < Mpad) ? 16u : 0u;
        const uint32_t szA1 = (r1 < Mpad) ? 16u : 0u;
        const uint32_t* s0h = g_hsh + (size_t)(rp * 128 + permS[r0]) * 256 + q * 4;
        const uint32_t* s0l = g_hsl + (size_t)(rp * 128 + permS[r0]) * 256 + q * 4;
        const uint32_t* s1h = g_hsh + (size_t)(rp * 128 + permS[r1]) * 256 + q * 4;
        const uint32_t* s1l = g_hsl + (size_t)(rp * 128 + permS[r1]) * 256 + q * 4;

        auto fill = [&](int s) {
            int buf = s & 1, ko = s * 16;
            uint32_t bo = buf * 2560 * 4;
            cpa16(aAh + bo + dA0, s0h + ko, szA0);
            cpa16(aAh + bo + dA1, s1h + ko, szA1);
            cpa16(aAl + bo + dA0, s0l + ko, szA0);
            cpa16(aAl + bo + dA1, s1l + ko, szA1);
            CP_COMMIT();
        };

        float d[4][4];
#pragma unroll
        for (int a = 0; a < 4; a++)
#pragma unroll
            for (int b = 0; b < 4; b++) d[a][b] = 0.f;

        fill(0);
        for (int ks = 0; ks < 16; ks++) {
            if (ks < 15) { fill(ks + 1); CP_WAIT(1); }
            else         { CP_WAIT(0); }
            __syncthreads();
            if (act) {
                const int buf = ks & 1;
                const uint32_t* Ah = sAh + buf * 2560;
                const uint32_t* Al = sAl + buf * 2560;
                const int r0w = w * 16 + rq;
#pragma unroll
                for (int kc = 0; kc < 2; kc++) {
                    int kb = kc * 8 + cq;
                    int kg = ks * 16 + kb;
                    uint32_t ah0 = Ah[r0w * 20 + kb],     ah1 = Ah[(r0w + 8) * 20 + kb];
                    uint32_t ah2 = Ah[r0w * 20 + kb + 4], ah3 = Ah[(r0w + 8) * 20 + kb + 4];
                    uint32_t al0 = Al[r0w * 20 + kb],     al1 = Al[(r0w + 8) * 20 + kb];
                    uint32_t al2 = Al[r0w * 20 + kb + 4], al3 = Al[(r0w + 8) * 20 + kb + 4];
#pragma unroll
                    for (int nt = 0; nt < 4; nt++) {
                        int n = nt * 8 + rq;
                        uint2 w0 = sW[n * 261 + kg];
                        uint2 w1 = sW[n * 261 + kg + 4];
                        mma16(d[nt], ah0, ah1, ah2, ah3, w0.x, w1.x);
                        mma16(d[nt], ah0, ah1, ah2, ah3, w0.y, w1.y);
                        mma16(d[nt], al0, al1, al2, al3, w0.x, w1.x);
                    }
                }
            }
            __syncthreads();
        }

        if (act) {
            const int wp = t & 1;
#pragma unroll
            for (int half = 0; half < 2; half++) {
                int rm = w * 16 + rq + half * 8;
                if (rm < Mc) {
                    int b = permS[rm];
                    int jj = j0 + cq * 2;
                    size_t xb = ((size_t)(t * 128 + b)) * GG + jj;
                    float2 xi = *(const float2*)(g_xg + xb);
                    float2 xf = *(const float2*)(g_xg + xb + 512);
                    float2 xg = *(const float2*)(g_xg + xb + 1024);
                    float2 xo = *(const float2*)(g_xg + xb + 1536);
                    float2 cc = __ldcg((const float2*)(g_c + b * HH + jj));
                    float i0 = sigm(xi.x + d[0][half * 2]);
                    float i1 = sigm(xi.y + d[0][half * 2 + 1]);
                    float f0 = sigm(xf.x + d[1][half * 2]);
                    float f1 = sigm(xf.y + d[1][half * 2 + 1]);
                    float gg0 = tanhf(xg.x + d[2][half * 2]);
                    float gg1 = tanhf(xg.y + d[2][half * 2 + 1]);
                    float o0 = sigm(xo.x + d[3][half * 2]);
                    float o1 = sigm(xo.y + d[3][half * 2 + 1]);
                    float c0 = f0 * cc.x + i0 * gg0;
                    float c1 = f1 * cc.y + i1 * gg1;
                    float h0 = o0 * tanhf(c0);
                    float h1 = o1 * tanhf(c1);
                    *(float2*)(g_c + b * HH + jj) = make_float2(c0, c1);
                    uint32_t hh, hl; split2(h0, h1, hh, hl);
                    int hi = (wp * 128 + b) * 256 + (j0 >> 1) + cq;
                    g_hsh[hi] = hh; g_hsl[hi] = hl;
                    *(float2*)(out + (size_t)b * (SS * HH) + t * HH + jj) = make_float2(h0, h1);
                }
            }
        }
        __threadfence();
        __syncthreads();
        if (tid == 0) {
            unsigned v = atomicAdd(&g_count, 1u) + 1u;
            if (v == 128u * (unsigned)(t + 1)) {
                asm volatile("st.release.gpu.u32 [%0], %1;" :: "l"(&g_release), "r"((unsigned)(t + 1)));
            }
        }
    }
}

__global__ void k_tail(float* __restrict__ out) {
    int i = blockIdx.x * 256 + threadIdx.x;
    if (i < BB * HH) {
        int b = i >> 9, j = i & 511;
        int hi = (128 + b) * 256 + (j >> 1);     // buf 1 (t=1023)
        uint32_t vh = g_hsh[hi], vl = g_hsl[hi];
        float h = (j & 1) ? (bf_hi(vh) + bf_hi(vl)) : (bf_lo(vh) + bf_lo(vl));
        out[(size_t)BSH + i] = h;
        out[(size_t)BSH + BB * HH + i] = g_c[i];
    }
}

extern "C" void kernel_launch(void* const* d_in, const int* in_sizes, int n_in,
                              void* d_out, int out_size) {
    const int*   inp   = (const int*)d_in[0];
    const float* embed = (const float*)d_in[1];
    const float* Wih   = (const float*)d_in[2];
    const float* Whh   = (const float*)d_in[3];
    const float* bih   = (const float*)d_in[4];
    const float* bhh   = (const float*)d_in[5];
    float* out = (float*)d_out;

    cudaFuncSetAttribute(k_phase1, cudaFuncAttributeMaxDynamicSharedMemorySize, SMEM1);
    cudaFuncSetAttribute(k_phase2, cudaFuncAttributeMaxDynamicSharedMemorySize, SMEM2);

    k_init<<<2120, 256>>>(bih, bhh, embed, Wih);
    k_setup<<<1, 1024>>>(inp);
    k_phase1<<<dim3(32, 1025), 256, SMEM1>>>();
    k_phase2<<<128, 256, SMEM2>>>(Whh, out);
    if (out_size >= BSH + 2 * BB * HH) k_tail<<<256, 256>>>(out);
}